// round 1
// baseline (speedup 1.0000x reference)
#include <cuda_runtime.h>
#include <cuda_bf16.h>
#include <cstddef>

#define D 128
#define MAXN 50000

// ---- scratch (allocation-free: __device__ globals) ----
__device__ float g_deg_out[MAXN];
__device__ float g_deg_in[MAXN];
__device__ float g_norm_src[MAXN];
__device__ float g_norm_dst[MAXN];
__device__ float g_h[(size_t)MAXN * D];    // layer-1 output
__device__ float g_agg[(size_t)MAXN * D];  // aggregation buffer

// ---- zero a float buffer (vectorized) ----
__global__ void k_zero4(float4* p, int n4) {
    int i = blockIdx.x * blockDim.x + threadIdx.x;
    if (i < n4) p[i] = make_float4(0.f, 0.f, 0.f, 0.f);
}

__global__ void k_zero(float* p, int n) {
    int i = blockIdx.x * blockDim.x + threadIdx.x;
    if (i < n) p[i] = 0.f;
}

// ---- degree counting ----
__global__ void k_deg(const int* __restrict__ src, const int* __restrict__ dst,
                      float* __restrict__ deg_out, float* __restrict__ deg_in, int E) {
    int i = blockIdx.x * blockDim.x + threadIdx.x;
    if (i < E) {
        atomicAdd(&deg_out[src[i]], 1.f);
        atomicAdd(&deg_in[dst[i]], 1.f);
    }
}

// ---- norms: clamp(deg,1)^-0.5 ----
__global__ void k_norm(const float* __restrict__ deg_out, const float* __restrict__ deg_in,
                       float* __restrict__ nsrc, float* __restrict__ ndst, int N) {
    int i = blockIdx.x * blockDim.x + threadIdx.x;
    if (i < N) {
        nsrc[i] = rsqrtf(fmaxf(deg_out[i], 1.f));
        ndst[i] = rsqrtf(fmaxf(deg_in[i], 1.f));
    }
}

// ---- edge scatter: one warp per edge; lane handles 4 consecutive floats ----
__global__ void k_scatter(const float* __restrict__ h, const int* __restrict__ src,
                          const int* __restrict__ dst, const float* __restrict__ nsrc,
                          float* __restrict__ agg, int E) {
    int e = (blockIdx.x * blockDim.x + threadIdx.x) >> 5;
    int lane = threadIdx.x & 31;
    if (e >= E) return;
    int s = __ldg(&src[e]);
    int d = __ldg(&dst[e]);
    float ns = __ldg(&nsrc[s]);
    float4 v = __ldg((const float4*)(h + (size_t)s * D) + lane);
    float* ap = agg + (size_t)d * D + lane * 4;
    atomicAdd(ap + 0, v.x * ns);
    atomicAdd(ap + 1, v.y * ns);
    atomicAdd(ap + 2, v.z * ns);
    atomicAdd(ap + 3, v.w * ns);
}

// ---- fused: C = relu((A * norm[:,None]) @ W + b); A:[N,128], W:[128,128] ----
// block = 256 threads computes 64 rows x 128 cols. tx = col-group (4 cols), ty row slice.
__global__ void k_gemm_bias_relu(const float* __restrict__ A, const float* __restrict__ Wm,
                                 const float* __restrict__ bias, const float* __restrict__ norm,
                                 float* __restrict__ C, int N) {
    __shared__ float Ws[32][128];   // k-tile x cols
    __shared__ float As[64][32];    // rows x k-tile

    int tid = threadIdx.x;
    int tx = tid & 31;   // 32 col groups of 4
    int ty = tid >> 5;   // 0..7
    int row0 = blockIdx.x * 64;

    float4 acc[8];
#pragma unroll
    for (int i = 0; i < 8; i++) acc[i] = make_float4(0.f, 0.f, 0.f, 0.f);

    for (int kt = 0; kt < 128; kt += 32) {
        // load W k-tile: 32x128 floats = 1024 float4, 4 per thread
#pragma unroll
        for (int j = 0; j < 4; j++) {
            int f = tid + j * 256;          // float4 index
            int kk = f >> 5;                // row within tile (32 float4/row)
            int c4 = f & 31;
            *(float4*)&Ws[kk][c4 * 4] =
                __ldg((const float4*)&Wm[(size_t)(kt + kk) * 128 + c4 * 4]);
        }
        // load A tile: 64x32 floats = 512 float4, 2 per thread (norm applied here)
#pragma unroll
        for (int j = 0; j < 2; j++) {
            int f = tid + j * 256;
            int rr = f >> 3;                // 8 float4 per row
            int k4 = f & 7;
            int grow = row0 + rr;
            float4 a = make_float4(0.f, 0.f, 0.f, 0.f);
            if (grow < N) {
                a = __ldg((const float4*)&A[(size_t)grow * 128 + kt + k4 * 4]);
                float nm = __ldg(&norm[grow]);
                a.x *= nm; a.y *= nm; a.z *= nm; a.w *= nm;
            }
            *(float4*)&As[rr][k4 * 4] = a;
        }
        __syncthreads();

#pragma unroll
        for (int k = 0; k < 32; k++) {
            float4 w = *(float4*)&Ws[k][tx * 4];
#pragma unroll
            for (int i = 0; i < 8; i++) {
                float a = As[ty + i * 8][k];
                acc[i].x = fmaf(a, w.x, acc[i].x);
                acc[i].y = fmaf(a, w.y, acc[i].y);
                acc[i].z = fmaf(a, w.z, acc[i].z);
                acc[i].w = fmaf(a, w.w, acc[i].w);
            }
        }
        __syncthreads();
    }

    float4 bv = __ldg((const float4*)&bias[tx * 4]);
#pragma unroll
    for (int i = 0; i < 8; i++) {
        int grow = row0 + ty + i * 8;
        if (grow < N) {
            float4 o;
            o.x = fmaxf(acc[i].x + bv.x, 0.f);
            o.y = fmaxf(acc[i].y + bv.y, 0.f);
            o.z = fmaxf(acc[i].z + bv.z, 0.f);
            o.w = fmaxf(acc[i].w + bv.w, 0.f);
            *(float4*)&C[(size_t)grow * 128 + tx * 4] = o;
        }
    }
}

extern "C" void kernel_launch(void* const* d_in, const int* in_sizes, int n_in,
                              void* d_out, int out_size) {
    const float* features = (const float*)d_in[0];
    const int* src = (const int*)d_in[1];
    const int* dst = (const int*)d_in[2];
    const float* W1 = (const float*)d_in[3];
    const float* b1 = (const float*)d_in[4];
    const float* W2 = (const float*)d_in[5];
    const float* b2 = (const float*)d_in[6];
    float* out = (float*)d_out;

    int N = in_sizes[0] / D;
    int E = in_sizes[1];

    float *deg_out, *deg_in, *nsrc, *ndst, *h1, *agg;
    cudaGetSymbolAddress((void**)&deg_out, g_deg_out);
    cudaGetSymbolAddress((void**)&deg_in, g_deg_in);
    cudaGetSymbolAddress((void**)&nsrc, g_norm_src);
    cudaGetSymbolAddress((void**)&ndst, g_norm_dst);
    cudaGetSymbolAddress((void**)&h1, g_h);
    cudaGetSymbolAddress((void**)&agg, g_agg);

    const int ZB = 256;
    // degrees
    k_zero<<<(N + ZB - 1) / ZB, ZB>>>(deg_out, N);
    k_zero<<<(N + ZB - 1) / ZB, ZB>>>(deg_in, N);
    k_deg<<<(E + ZB - 1) / ZB, ZB>>>(src, dst, deg_out, deg_in, E);
    k_norm<<<(N + ZB - 1) / ZB, ZB>>>(deg_out, deg_in, nsrc, ndst, N);

    int n4 = N * D / 4;
    int scat_blocks = (E * 32 + ZB - 1) / ZB;
    int gemm_blocks = (N + 63) / 64;

    // layer 1: features -> h1
    k_zero4<<<(n4 + ZB - 1) / ZB, ZB>>>((float4*)agg, n4);
    k_scatter<<<scat_blocks, ZB>>>(features, src, dst, nsrc, agg, E);
    k_gemm_bias_relu<<<gemm_blocks, 256>>>(agg, W1, b1, ndst, h1, N);

    // layer 2: h1 -> out
    k_zero4<<<(n4 + ZB - 1) / ZB, ZB>>>((float4*)agg, n4);
    k_scatter<<<scat_blocks, ZB>>>(h1, src, dst, nsrc, agg, E);
    k_gemm_bias_relu<<<gemm_blocks, 256>>>(agg, W2, b2, ndst, out, N);
}

// round 2
// speedup vs baseline: 1.8309x; 1.8309x over previous
#include <cuda_runtime.h>
#include <cuda_bf16.h>
#include <cstddef>

#define D 128
#define MAXN 50000

// ---- scratch (allocation-free: __device__ globals) ----
__device__ float g_deg_out[MAXN];
__device__ float g_deg_in[MAXN];
__device__ float g_norm_src[MAXN];
__device__ float g_norm_dst[MAXN];
__device__ float g_h[(size_t)MAXN * D];    // layer-1 output
__device__ float g_agg[(size_t)MAXN * D];  // aggregation buffer

// ---- zero a float buffer (vectorized) ----
__global__ void k_zero4(float4* p, int n4) {
    int i = blockIdx.x * blockDim.x + threadIdx.x;
    if (i < n4) p[i] = make_float4(0.f, 0.f, 0.f, 0.f);
}

__global__ void k_zero(float* p, int n) {
    int i = blockIdx.x * blockDim.x + threadIdx.x;
    if (i < n) p[i] = 0.f;
}

// ---- degree counting ----
__global__ void k_deg(const int* __restrict__ src, const int* __restrict__ dst,
                      float* __restrict__ deg_out, float* __restrict__ deg_in, int E) {
    int i = blockIdx.x * blockDim.x + threadIdx.x;
    if (i < E) {
        atomicAdd(&deg_out[src[i]], 1.f);
        atomicAdd(&deg_in[dst[i]], 1.f);
    }
}

// ---- norms: clamp(deg,1)^-0.5 ----
__global__ void k_norm(const float* __restrict__ deg_out, const float* __restrict__ deg_in,
                       float* __restrict__ nsrc, float* __restrict__ ndst, int N) {
    int i = blockIdx.x * blockDim.x + threadIdx.x;
    if (i < N) {
        nsrc[i] = rsqrtf(fmaxf(deg_out[i], 1.f));
        ndst[i] = rsqrtf(fmaxf(deg_in[i], 1.f));
    }
}

// ---- vectorized 16B global reduction ----
__device__ __forceinline__ void red_add_v4(float* addr, float4 v) {
    asm volatile("red.global.add.v4.f32 [%0], {%1, %2, %3, %4};"
                 :: "l"(addr), "f"(v.x), "f"(v.y), "f"(v.z), "f"(v.w)
                 : "memory");
}

// ---- edge scatter: one warp per edge; lane handles 4 consecutive floats ----
__global__ void k_scatter(const float* __restrict__ h, const int* __restrict__ src,
                          const int* __restrict__ dst, const float* __restrict__ nsrc,
                          float* __restrict__ agg, int E) {
    int e = (blockIdx.x * blockDim.x + threadIdx.x) >> 5;
    int lane = threadIdx.x & 31;
    if (e >= E) return;
    int s = __ldg(&src[e]);
    int d = __ldg(&dst[e]);
    float ns = __ldg(&nsrc[s]);
    float4 v = __ldg((const float4*)(h + (size_t)s * D) + lane);
    v.x *= ns; v.y *= ns; v.z *= ns; v.w *= ns;
    red_add_v4(agg + (size_t)d * D + lane * 4, v);
}

// ---- fused: C = relu((A * norm[:,None]) @ W + b); A:[N,128], W:[128,128] ----
// block = 256 threads computes 64 rows x 128 cols. tx = col-group (4 cols), ty row slice.
__global__ void k_gemm_bias_relu(const float* __restrict__ A, const float* __restrict__ Wm,
                                 const float* __restrict__ bias, const float* __restrict__ norm,
                                 float* __restrict__ C, int N) {
    __shared__ float Ws[32][128];   // k-tile x cols
    __shared__ float As[64][32];    // rows x k-tile

    int tid = threadIdx.x;
    int tx = tid & 31;   // 32 col groups of 4
    int ty = tid >> 5;   // 0..7
    int row0 = blockIdx.x * 64;

    float4 acc[8];
#pragma unroll
    for (int i = 0; i < 8; i++) acc[i] = make_float4(0.f, 0.f, 0.f, 0.f);

    for (int kt = 0; kt < 128; kt += 32) {
        // load W k-tile: 32x128 floats = 1024 float4, 4 per thread
#pragma unroll
        for (int j = 0; j < 4; j++) {
            int f = tid + j * 256;          // float4 index
            int kk = f >> 5;                // row within tile (32 float4/row)
            int c4 = f & 31;
            *(float4*)&Ws[kk][c4 * 4] =
                __ldg((const float4*)&Wm[(size_t)(kt + kk) * 128 + c4 * 4]);
        }
        // load A tile: 64x32 floats = 512 float4, 2 per thread (norm applied here)
#pragma unroll
        for (int j = 0; j < 2; j++) {
            int f = tid + j * 256;
            int rr = f >> 3;                // 8 float4 per row
            int k4 = f & 7;
            int grow = row0 + rr;
            float4 a = make_float4(0.f, 0.f, 0.f, 0.f);
            if (grow < N) {
                a = __ldg((const float4*)&A[(size_t)grow * 128 + kt + k4 * 4]);
                float nm = __ldg(&norm[grow]);
                a.x *= nm; a.y *= nm; a.z *= nm; a.w *= nm;
            }
            *(float4*)&As[rr][k4 * 4] = a;
        }
        __syncthreads();

#pragma unroll
        for (int k = 0; k < 32; k++) {
            float4 w = *(float4*)&Ws[k][tx * 4];
#pragma unroll
            for (int i = 0; i < 8; i++) {
                float a = As[ty + i * 8][k];
                acc[i].x = fmaf(a, w.x, acc[i].x);
                acc[i].y = fmaf(a, w.y, acc[i].y);
                acc[i].z = fmaf(a, w.z, acc[i].z);
                acc[i].w = fmaf(a, w.w, acc[i].w);
            }
        }
        __syncthreads();
    }

    float4 bv = __ldg((const float4*)&bias[tx * 4]);
#pragma unroll
    for (int i = 0; i < 8; i++) {
        int grow = row0 + ty + i * 8;
        if (grow < N) {
            float4 o;
            o.x = fmaxf(acc[i].x + bv.x, 0.f);
            o.y = fmaxf(acc[i].y + bv.y, 0.f);
            o.z = fmaxf(acc[i].z + bv.z, 0.f);
            o.w = fmaxf(acc[i].w + bv.w, 0.f);
            *(float4*)&C[(size_t)grow * 128 + tx * 4] = o;
        }
    }
}

extern "C" void kernel_launch(void* const* d_in, const int* in_sizes, int n_in,
                              void* d_out, int out_size) {
    const float* features = (const float*)d_in[0];
    const int* src = (const int*)d_in[1];
    const int* dst = (const int*)d_in[2];
    const float* W1 = (const float*)d_in[3];
    const float* b1 = (const float*)d_in[4];
    const float* W2 = (const float*)d_in[5];
    const float* b2 = (const float*)d_in[6];
    float* out = (float*)d_out;

    int N = in_sizes[0] / D;
    int E = in_sizes[1];

    float *deg_out, *deg_in, *nsrc, *ndst, *h1, *agg;
    cudaGetSymbolAddress((void**)&deg_out, g_deg_out);
    cudaGetSymbolAddress((void**)&deg_in, g_deg_in);
    cudaGetSymbolAddress((void**)&nsrc, g_norm_src);
    cudaGetSymbolAddress((void**)&ndst, g_norm_dst);
    cudaGetSymbolAddress((void**)&h1, g_h);
    cudaGetSymbolAddress((void**)&agg, g_agg);

    const int ZB = 256;
    // degrees
    k_zero<<<(N + ZB - 1) / ZB, ZB>>>(deg_out, N);
    k_zero<<<(N + ZB - 1) / ZB, ZB>>>(deg_in, N);
    k_deg<<<(E + ZB - 1) / ZB, ZB>>>(src, dst, deg_out, deg_in, E);
    k_norm<<<(N + ZB - 1) / ZB, ZB>>>(deg_out, deg_in, nsrc, ndst, N);

    int n4 = N * D / 4;
    int scat_blocks = (E * 32 + ZB - 1) / ZB;
    int gemm_blocks = (N + 63) / 64;

    // layer 1: features -> h1
    k_zero4<<<(n4 + ZB - 1) / ZB, ZB>>>((float4*)agg, n4);
    k_scatter<<<scat_blocks, ZB>>>(features, src, dst, nsrc, agg, E);
    k_gemm_bias_relu<<<gemm_blocks, 256>>>(agg, W1, b1, ndst, h1, N);

    // layer 2: h1 -> out
    k_zero4<<<(n4 + ZB - 1) / ZB, ZB>>>((float4*)agg, n4);
    k_scatter<<<scat_blocks, ZB>>>(h1, src, dst, nsrc, agg, E);
    k_gemm_bias_relu<<<gemm_blocks, 256>>>(agg, W2, b2, ndst, out, N);
}

// round 4
// speedup vs baseline: 2.2393x; 1.2231x over previous
#include <cuda_runtime.h>
#include <cuda_bf16.h>
#include <cstdint>
#include <cstddef>

#define D 128
#define MAXN 50000

// ---- scratch (allocation-free: __device__ globals; zero-initialized at load) ----
__device__ float g_deg_out[MAXN];
__device__ float g_deg_in[MAXN];
__device__ float g_norm_src[MAXN];
__device__ float g_norm_dst[MAXN];
__device__ float g_h[(size_t)MAXN * D];    // layer-1 output
__device__ float g_agg[(size_t)MAXN * D];  // aggregation buffer (re-zeroed by GEMM epilogue)

__global__ void k_zero(float* p, int n) {
    int i = blockIdx.x * blockDim.x + threadIdx.x;
    if (i < n) p[i] = 0.f;
}

// ---- degree counting ----
__global__ void k_deg(const int* __restrict__ src, const int* __restrict__ dst,
                      float* __restrict__ deg_out, float* __restrict__ deg_in, int E) {
    int i = blockIdx.x * blockDim.x + threadIdx.x;
    if (i < E) {
        atomicAdd(&deg_out[src[i]], 1.f);
        atomicAdd(&deg_in[dst[i]], 1.f);
    }
}

// ---- norms: clamp(deg,1)^-0.5 ----
__global__ void k_norm(const float* __restrict__ deg_out, const float* __restrict__ deg_in,
                       float* __restrict__ nsrc, float* __restrict__ ndst, int N) {
    int i = blockIdx.x * blockDim.x + threadIdx.x;
    if (i < N) {
        nsrc[i] = rsqrtf(fmaxf(deg_out[i], 1.f));
        ndst[i] = rsqrtf(fmaxf(deg_in[i], 1.f));
    }
}

// ---- vectorized 16B global reduction ----
__device__ __forceinline__ void red_add_v4(float* addr, float4 v) {
    asm volatile("red.global.add.v4.f32 [%0], {%1, %2, %3, %4};"
                 :: "l"(addr), "f"(v.x), "f"(v.y), "f"(v.z), "f"(v.w)
                 : "memory");
}

// ---- edge scatter: one warp per edge; lane handles 4 consecutive floats ----
__global__ void k_scatter(const float* __restrict__ h, const int* __restrict__ src,
                          const int* __restrict__ dst, const float* __restrict__ nsrc,
                          float* __restrict__ agg, int E) {
    int e = (blockIdx.x * blockDim.x + threadIdx.x) >> 5;
    int lane = threadIdx.x & 31;
    if (e >= E) return;
    int s = __ldg(&src[e]);
    int d = __ldg(&dst[e]);
    float ns = __ldg(&nsrc[s]);
    float4 v = __ldg((const float4*)(h + (size_t)s * D) + lane);
    v.x *= ns; v.y *= ns; v.z *= ns; v.w *= ns;
    red_add_v4(agg + (size_t)d * D + lane * 4, v);
}

// ---- tf32 helpers ----
__device__ __forceinline__ uint32_t f2tf32(float x) {
    uint32_t r;
    asm("cvt.rna.tf32.f32 %0, %1;" : "=r"(r) : "f"(x));
    return r;
}

__device__ __forceinline__ void mma_tf32(float* c, uint32_t a0, uint32_t a1,
                                         uint32_t a2, uint32_t a3,
                                         uint32_t b0, uint32_t b1) {
    asm volatile(
        "mma.sync.aligned.m16n8k8.row.col.f32.tf32.tf32.f32 "
        "{%0,%1,%2,%3}, {%4,%5,%6,%7}, {%8,%9}, {%0,%1,%2,%3};"
        : "+f"(c[0]), "+f"(c[1]), "+f"(c[2]), "+f"(c[3])
        : "r"(a0), "r"(a1), "r"(a2), "r"(a3), "r"(b0), "r"(b1));
}

// ---- fused: C = relu((A * norm[:,None]) @ W + b); then zero A (for next scatter) ----
// block = 256 threads (8 warps), tile 128 rows x 128 cols. tf32 tensor cores.
#define AS_STRIDE 36    // bank = (4*row + k) % 32 -> conflict-free fragment loads
#define WS_STRIDE 136   // bank = (8*t + g) % 32  -> conflict-free fragment loads

__global__ __launch_bounds__(256)
void k_gemm_tf32(const float* __restrict__ A, const float* __restrict__ Wm,
                 const float* __restrict__ bias, const float* __restrict__ norm,
                 float* __restrict__ C, float* __restrict__ Azero, int N) {
    __shared__ uint32_t As[128 * AS_STRIDE];
    __shared__ uint32_t Ws[32 * WS_STRIDE];

    const int tid = threadIdx.x;
    const int warp = tid >> 5;
    const int lane = tid & 31;
    const int g = lane >> 2;    // group id 0..7
    const int t = lane & 3;     // thread-in-group 0..3
    const int row0 = blockIdx.x * 128;

    float acc[16][4];
#pragma unroll
    for (int j = 0; j < 16; j++)
#pragma unroll
        for (int i = 0; i < 4; i++) acc[j][i] = 0.f;

    for (int kt = 0; kt < 128; kt += 32) {
        // stage W k-tile [32][128] -> Ws (tf32), 4 float4/thread
#pragma unroll
        for (int j = 0; j < 4; j++) {
            int f = tid + j * 256;      // float4 index 0..1023
            int kk = f >> 5;            // 0..31
            int c4 = f & 31;            // 0..31
            float4 w = __ldg((const float4*)&Wm[(size_t)(kt + kk) * 128 + c4 * 4]);
            uint32_t* p = &Ws[kk * WS_STRIDE + c4 * 4];
            p[0] = f2tf32(w.x); p[1] = f2tf32(w.y); p[2] = f2tf32(w.z); p[3] = f2tf32(w.w);
        }
        // stage A k-tile [128][32] -> As (tf32, norm fused), 4 float4/thread
#pragma unroll
        for (int j = 0; j < 4; j++) {
            int f = tid + j * 256;      // float4 index 0..1023
            int rr = f >> 3;            // row 0..127 (8 float4 per 32-float k-tile row)
            int c4 = f & 7;             // 0..7
            int grow = row0 + rr;
            float4 a = make_float4(0.f, 0.f, 0.f, 0.f);
            if (grow < N) {
                a = __ldg((const float4*)&A[(size_t)grow * 128 + kt + c4 * 4]);
                float nm = __ldg(&norm[grow]);
                a.x *= nm; a.y *= nm; a.z *= nm; a.w *= nm;
            }
            uint32_t* p = &As[rr * AS_STRIDE + c4 * 4];
            p[0] = f2tf32(a.x); p[1] = f2tf32(a.y); p[2] = f2tf32(a.z); p[3] = f2tf32(a.w);
        }
        __syncthreads();

#pragma unroll
        for (int k8 = 0; k8 < 4; k8++) {
            int kb = k8 * 8;
            int r = warp * 16;
            uint32_t a0 = As[(r + g) * AS_STRIDE + kb + t];
            uint32_t a1 = As[(r + g + 8) * AS_STRIDE + kb + t];
            uint32_t a2 = As[(r + g) * AS_STRIDE + kb + t + 4];
            uint32_t a3 = As[(r + g + 8) * AS_STRIDE + kb + t + 4];
#pragma unroll
            for (int j = 0; j < 16; j++) {
                uint32_t b0 = Ws[(kb + t) * WS_STRIDE + j * 8 + g];
                uint32_t b1 = Ws[(kb + t + 4) * WS_STRIDE + j * 8 + g];
                mma_tf32(acc[j], a0, a1, a2, a3, b0, b1);
            }
        }
        __syncthreads();
    }

    // epilogue: bias + relu, write C
    const int r1 = row0 + warp * 16 + g;
    const int r2 = r1 + 8;
#pragma unroll
    for (int j = 0; j < 16; j++) {
        int col = j * 8 + 2 * t;
        float2 bv = *(const float2*)&bias[col];
        if (r1 < N) {
            float2 o;
            o.x = fmaxf(acc[j][0] + bv.x, 0.f);
            o.y = fmaxf(acc[j][1] + bv.y, 0.f);
            *(float2*)&C[(size_t)r1 * 128 + col] = o;
        }
        if (r2 < N) {
            float2 o;
            o.x = fmaxf(acc[j][2] + bv.x, 0.f);
            o.y = fmaxf(acc[j][3] + bv.y, 0.f);
            *(float2*)&C[(size_t)r2 * 128 + col] = o;
        }
    }

    // zero this block's OWN A rows (prepares agg for the next scatter / next replay).
    // Tile = 128 rows x 32 float4/row = 4096 float4; 16 per thread.
    // rr = f>>5 (0..127), c4 = f&31 (0..31)  -- FIXED indexing (was f>>3 / f&7).
#pragma unroll
    for (int j = 0; j < 16; j++) {
        int f = tid + j * 256;
        int rr = f >> 5;
        int c4 = f & 31;
        int grow = row0 + rr;
        if (grow < N)
            *(float4*)&Azero[(size_t)grow * 128 + c4 * 4] = make_float4(0.f, 0.f, 0.f, 0.f);
    }
}

extern "C" void kernel_launch(void* const* d_in, const int* in_sizes, int n_in,
                              void* d_out, int out_size) {
    const float* features = (const float*)d_in[0];
    const int* src = (const int*)d_in[1];
    const int* dst = (const int*)d_in[2];
    const float* W1 = (const float*)d_in[3];
    const float* b1 = (const float*)d_in[4];
    const float* W2 = (const float*)d_in[5];
    const float* b2 = (const float*)d_in[6];
    float* out = (float*)d_out;

    int N = in_sizes[0] / D;
    int E = in_sizes[1];

    float *deg_out, *deg_in, *nsrc, *ndst, *h1, *agg;
    cudaGetSymbolAddress((void**)&deg_out, g_deg_out);
    cudaGetSymbolAddress((void**)&deg_in, g_deg_in);
    cudaGetSymbolAddress((void**)&nsrc, g_norm_src);
    cudaGetSymbolAddress((void**)&ndst, g_norm_dst);
    cudaGetSymbolAddress((void**)&h1, g_h);
    cudaGetSymbolAddress((void**)&agg, g_agg);

    const int ZB = 256;
    // degrees + norms
    k_zero<<<(N + ZB - 1) / ZB, ZB>>>(deg_out, N);
    k_zero<<<(N + ZB - 1) / ZB, ZB>>>(deg_in, N);
    k_deg<<<(E + ZB - 1) / ZB, ZB>>>(src, dst, deg_out, deg_in, E);
    k_norm<<<(N + ZB - 1) / ZB, ZB>>>(deg_out, deg_in, nsrc, ndst, N);

    int scat_blocks = (E * 32 + ZB - 1) / ZB;
    int gemm_blocks = (N + 127) / 128;

    // layer 1: features -> h1   (agg zeroed: initially by static init, then by GEMM epilogues)
    k_scatter<<<scat_blocks, ZB>>>(features, src, dst, nsrc, agg, E);
    k_gemm_tf32<<<gemm_blocks, 256>>>(agg, W1, b1, ndst, h1, agg, N);

    // layer 2: h1 -> out
    k_scatter<<<scat_blocks, ZB>>>(h1, src, dst, nsrc, agg, E);
    k_gemm_tf32<<<gemm_blocks, 256>>>(agg, W2, b2, ndst, out, agg, N);
}

// round 5
// speedup vs baseline: 3.4396x; 1.5360x over previous
#include <cuda_runtime.h>
#include <cuda_bf16.h>
#include <cstdint>
#include <cstddef>

#define D 128
#define MAXN 50000
#define MAXE 600064
#define SCAN_B 256
#define MAXNB ((MAXN + SCAN_B - 1) / SCAN_B)   // 196

// ---- scratch (allocation-free: __device__ globals) ----
__device__ int   g_cnt_out[MAXN];
__device__ int   g_cnt_in[MAXN];
__device__ float g_norm_src[MAXN];
__device__ float g_norm_dst[MAXN];
__device__ int   g_row_start[MAXN];
__device__ int   g_cursor[MAXN];
__device__ int   g_blk_sums[SCAN_B];           // >= MAXNB
__device__ int   g_sorted_src[MAXE];
__device__ float g_h[(size_t)MAXN * D];        // layer-1 output
__device__ float g_agg[(size_t)MAXN * D];      // aggregation buffer

// ---- zero int counters ----
__global__ void k_zero2i(int* a, int* b, int n) {
    int i = blockIdx.x * blockDim.x + threadIdx.x;
    if (i < n) { a[i] = 0; b[i] = 0; }
}

// ---- degree histogram ----
__global__ void k_hist(const int* __restrict__ src, const int* __restrict__ dst,
                       int* __restrict__ cnt_out, int* __restrict__ cnt_in, int E) {
    int i = blockIdx.x * blockDim.x + threadIdx.x;
    if (i < E) {
        atomicAdd(&cnt_out[src[i]], 1);
        atomicAdd(&cnt_in[dst[i]], 1);
    }
}

// ---- norms ----
__global__ void k_norm(const int* __restrict__ cnt_out, const int* __restrict__ cnt_in,
                       float* __restrict__ nsrc, float* __restrict__ ndst, int N) {
    int i = blockIdx.x * blockDim.x + threadIdx.x;
    if (i < N) {
        nsrc[i] = rsqrtf(fmaxf((float)cnt_out[i], 1.f));
        ndst[i] = rsqrtf(fmaxf((float)cnt_in[i], 1.f));
    }
}

// ---- exclusive scan (3 phases, 256-wide blocks) ----
__global__ void k_scan_block(const int* __restrict__ cnt, int* __restrict__ excl,
                             int* __restrict__ blk_sums, int N) {
    __shared__ int sh[SCAN_B];
    int i = blockIdx.x * SCAN_B + threadIdx.x;
    int v = (i < N) ? cnt[i] : 0;
    sh[threadIdx.x] = v; __syncthreads();
#pragma unroll
    for (int off = 1; off < SCAN_B; off <<= 1) {
        int t = (threadIdx.x >= off) ? sh[threadIdx.x - off] : 0;
        __syncthreads();
        sh[threadIdx.x] += t;
        __syncthreads();
    }
    if (i < N) excl[i] = sh[threadIdx.x] - v;
    if (threadIdx.x == SCAN_B - 1) blk_sums[blockIdx.x] = sh[SCAN_B - 1];
}

__global__ void k_scan_tops(int* __restrict__ blk_sums, int nb) {
    __shared__ int sh[SCAN_B];
    int v = (threadIdx.x < nb) ? blk_sums[threadIdx.x] : 0;
    sh[threadIdx.x] = v; __syncthreads();
#pragma unroll
    for (int off = 1; off < SCAN_B; off <<= 1) {
        int t = (threadIdx.x >= off) ? sh[threadIdx.x - off] : 0;
        __syncthreads();
        sh[threadIdx.x] += t;
        __syncthreads();
    }
    if (threadIdx.x < nb) blk_sums[threadIdx.x] = sh[threadIdx.x] - v;  // exclusive
}

__global__ void k_scan_add(int* __restrict__ excl, const int* __restrict__ blk_sums,
                           int* __restrict__ cursor, int N) {
    int i = blockIdx.x * SCAN_B + threadIdx.x;
    if (i < N) {
        int r = excl[i] + blk_sums[blockIdx.x];
        excl[i] = r;
        cursor[i] = r;
    }
}

// ---- bucket edges by dst: CSR src list ----
__global__ void k_bucket(const int* __restrict__ src, const int* __restrict__ dst,
                         int* __restrict__ cursor, int* __restrict__ sorted_src, int E) {
    int i = blockIdx.x * blockDim.x + threadIdx.x;
    if (i < E) {
        int pos = atomicAdd(&cursor[dst[i]], 1);
        sorted_src[pos] = src[i];
    }
}

// ---- atomic-free aggregation: warp per dst node ----
__global__ void k_gather(const float* __restrict__ h, const int* __restrict__ sorted_src,
                         const int* __restrict__ row_start, const int* __restrict__ cnt_in,
                         const float* __restrict__ nsrc, float* __restrict__ agg, int N) {
    int n = (blockIdx.x * blockDim.x + threadIdx.x) >> 5;
    int lane = threadIdx.x & 31;
    if (n >= N) return;
    int start = __ldg(&row_start[n]);
    int cnt = __ldg(&cnt_in[n]);
    float4 acc = make_float4(0.f, 0.f, 0.f, 0.f);
    int j = 0;
    for (; j + 2 <= cnt; j += 2) {
        int s0 = __ldg(&sorted_src[start + j]);
        int s1 = __ldg(&sorted_src[start + j + 1]);
        float ns0 = __ldg(&nsrc[s0]);
        float ns1 = __ldg(&nsrc[s1]);
        float4 v0 = __ldg((const float4*)(h + (size_t)s0 * D) + lane);
        float4 v1 = __ldg((const float4*)(h + (size_t)s1 * D) + lane);
        acc.x = fmaf(ns0, v0.x, acc.x); acc.y = fmaf(ns0, v0.y, acc.y);
        acc.z = fmaf(ns0, v0.z, acc.z); acc.w = fmaf(ns0, v0.w, acc.w);
        acc.x = fmaf(ns1, v1.x, acc.x); acc.y = fmaf(ns1, v1.y, acc.y);
        acc.z = fmaf(ns1, v1.z, acc.z); acc.w = fmaf(ns1, v1.w, acc.w);
    }
    if (j < cnt) {
        int s = __ldg(&sorted_src[start + j]);
        float ns = __ldg(&nsrc[s]);
        float4 v = __ldg((const float4*)(h + (size_t)s * D) + lane);
        acc.x = fmaf(ns, v.x, acc.x); acc.y = fmaf(ns, v.y, acc.y);
        acc.z = fmaf(ns, v.z, acc.z); acc.w = fmaf(ns, v.w, acc.w);
    }
    *((float4*)(agg + (size_t)n * D) + lane) = acc;
}

// ---- tf32 helpers ----
__device__ __forceinline__ uint32_t f2tf32(float x) {
    uint32_t r;
    asm("cvt.rna.tf32.f32 %0, %1;" : "=r"(r) : "f"(x));
    return r;
}

__device__ __forceinline__ void mma_tf32(float* c, uint32_t a0, uint32_t a1,
                                         uint32_t a2, uint32_t a3,
                                         uint32_t b0, uint32_t b1) {
    asm volatile(
        "mma.sync.aligned.m16n8k8.row.col.f32.tf32.tf32.f32 "
        "{%0,%1,%2,%3}, {%4,%5,%6,%7}, {%8,%9}, {%0,%1,%2,%3};"
        : "+f"(c[0]), "+f"(c[1]), "+f"(c[2]), "+f"(c[3])
        : "r"(a0), "r"(a1), "r"(a2), "r"(a3), "r"(b0), "r"(b1));
}

// ---- fused: C = relu((A * norm[:,None]) @ W + b) ----
#define AS_STRIDE 36
#define WS_STRIDE 136

__global__ __launch_bounds__(256)
void k_gemm_tf32(const float* __restrict__ A, const float* __restrict__ Wm,
                 const float* __restrict__ bias, const float* __restrict__ norm,
                 float* __restrict__ C, int N) {
    __shared__ uint32_t As[128 * AS_STRIDE];
    __shared__ uint32_t Ws[32 * WS_STRIDE];

    const int tid = threadIdx.x;
    const int warp = tid >> 5;
    const int lane = tid & 31;
    const int g = lane >> 2;
    const int t = lane & 3;
    const int row0 = blockIdx.x * 128;

    float acc[16][4];
#pragma unroll
    for (int j = 0; j < 16; j++)
#pragma unroll
        for (int i = 0; i < 4; i++) acc[j][i] = 0.f;

    for (int kt = 0; kt < 128; kt += 32) {
#pragma unroll
        for (int j = 0; j < 4; j++) {
            int f = tid + j * 256;
            int kk = f >> 5;
            int c4 = f & 31;
            float4 w = __ldg((const float4*)&Wm[(size_t)(kt + kk) * 128 + c4 * 4]);
            uint32_t* p = &Ws[kk * WS_STRIDE + c4 * 4];
            p[0] = f2tf32(w.x); p[1] = f2tf32(w.y); p[2] = f2tf32(w.z); p[3] = f2tf32(w.w);
        }
#pragma unroll
        for (int j = 0; j < 4; j++) {
            int f = tid + j * 256;
            int rr = f >> 3;
            int c4 = f & 7;
            int grow = row0 + rr;
            float4 a = make_float4(0.f, 0.f, 0.f, 0.f);
            if (grow < N) {
                a = __ldg((const float4*)&A[(size_t)grow * 128 + kt + c4 * 4]);
                float nm = __ldg(&norm[grow]);
                a.x *= nm; a.y *= nm; a.z *= nm; a.w *= nm;
            }
            uint32_t* p = &As[rr * AS_STRIDE + c4 * 4];
            p[0] = f2tf32(a.x); p[1] = f2tf32(a.y); p[2] = f2tf32(a.z); p[3] = f2tf32(a.w);
        }
        __syncthreads();

#pragma unroll
        for (int k8 = 0; k8 < 4; k8++) {
            int kb = k8 * 8;
            int r = warp * 16;
            uint32_t a0 = As[(r + g) * AS_STRIDE + kb + t];
            uint32_t a1 = As[(r + g + 8) * AS_STRIDE + kb + t];
            uint32_t a2 = As[(r + g) * AS_STRIDE + kb + t + 4];
            uint32_t a3 = As[(r + g + 8) * AS_STRIDE + kb + t + 4];
#pragma unroll
            for (int j = 0; j < 16; j++) {
                uint32_t b0 = Ws[(kb + t) * WS_STRIDE + j * 8 + g];
                uint32_t b1 = Ws[(kb + t + 4) * WS_STRIDE + j * 8 + g];
                mma_tf32(acc[j], a0, a1, a2, a3, b0, b1);
            }
        }
        __syncthreads();
    }

    const int r1 = row0 + warp * 16 + g;
    const int r2 = r1 + 8;
#pragma unroll
    for (int j = 0; j < 16; j++) {
        int col = j * 8 + 2 * t;
        float2 bv = *(const float2*)&bias[col];
        if (r1 < N) {
            float2 o;
            o.x = fmaxf(acc[j][0] + bv.x, 0.f);
            o.y = fmaxf(acc[j][1] + bv.y, 0.f);
            *(float2*)&C[(size_t)r1 * 128 + col] = o;
        }
        if (r2 < N) {
            float2 o;
            o.x = fmaxf(acc[j][2] + bv.x, 0.f);
            o.y = fmaxf(acc[j][3] + bv.y, 0.f);
            *(float2*)&C[(size_t)r2 * 128 + col] = o;
        }
    }
}

extern "C" void kernel_launch(void* const* d_in, const int* in_sizes, int n_in,
                              void* d_out, int out_size) {
    const float* features = (const float*)d_in[0];
    const int* src = (const int*)d_in[1];
    const int* dst = (const int*)d_in[2];
    const float* W1 = (const float*)d_in[3];
    const float* b1 = (const float*)d_in[4];
    const float* W2 = (const float*)d_in[5];
    const float* b2 = (const float*)d_in[6];
    float* out = (float*)d_out;

    int N = in_sizes[0] / D;
    int E = in_sizes[1];

    int *cnt_out, *cnt_in, *row_start, *cursor, *blk_sums, *sorted_src;
    float *nsrc, *ndst, *h1, *agg;
    cudaGetSymbolAddress((void**)&cnt_out, g_cnt_out);
    cudaGetSymbolAddress((void**)&cnt_in, g_cnt_in);
    cudaGetSymbolAddress((void**)&row_start, g_row_start);
    cudaGetSymbolAddress((void**)&cursor, g_cursor);
    cudaGetSymbolAddress((void**)&blk_sums, g_blk_sums);
    cudaGetSymbolAddress((void**)&sorted_src, g_sorted_src);
    cudaGetSymbolAddress((void**)&nsrc, g_norm_src);
    cudaGetSymbolAddress((void**)&ndst, g_norm_dst);
    cudaGetSymbolAddress((void**)&h1, g_h);
    cudaGetSymbolAddress((void**)&agg, g_agg);

    const int ZB = 256;
    int nblkN = (N + ZB - 1) / ZB;
    int nblkE = (E + ZB - 1) / ZB;

    // degrees + norms + CSR build
    k_zero2i<<<nblkN, ZB>>>(cnt_out, cnt_in, N);
    k_hist<<<nblkE, ZB>>>(src, dst, cnt_out, cnt_in, E);
    k_norm<<<nblkN, ZB>>>(cnt_out, cnt_in, nsrc, ndst, N);
    k_scan_block<<<nblkN, SCAN_B>>>(cnt_in, row_start, blk_sums, N);
    k_scan_tops<<<1, SCAN_B>>>(blk_sums, nblkN);
    k_scan_add<<<nblkN, SCAN_B>>>(row_start, blk_sums, cursor, N);
    k_bucket<<<nblkE, ZB>>>(src, dst, cursor, sorted_src, E);

    int gath_blocks = (N * 32 + ZB - 1) / ZB;
    int gemm_blocks = (N + 127) / 128;

    // layer 1
    k_gather<<<gath_blocks, ZB>>>(features, sorted_src, row_start, cnt_in, nsrc, agg, N);
    k_gemm_tf32<<<gemm_blocks, 256>>>(agg, W1, b1, ndst, h1, N);

    // layer 2
    k_gather<<<gath_blocks, ZB>>>(h1, sorted_src, row_start, cnt_in, nsrc, agg, N);
    k_gemm_tf32<<<gemm_blocks, 256>>>(agg, W2, b2, ndst, out, N);
}